// round 1
// baseline (speedup 1.0000x reference)
#include <cuda_runtime.h>

// ---------------------------------------------------------------------------
// TempoJelly: s2 = ((x @ W1^T >= 1) @ W2^T >= 1)
//   x  [4096, 3136] binary fp32
//   W1 [6272, 3136] fp32 (row-major, K contiguous)
//   W2 [ 500, 6272] fp32 (row-major, K contiguous)
//   out[4096,  500] fp32 in {0,1}
//
// Round 1: fp32 SIMT tiled SGEMM (NT layout: both operands K-major) with the
// IF-neuron threshold fused into the epilogue. Intermediate hidden spikes s1
// live in a static __device__ buffer (alloc-guard-safe, graph-capturable).
// ---------------------------------------------------------------------------

#define BM 128
#define BN 128
#define BK 16
#define TM 8
#define TN 8

// 4096 * 6272 floats = 102.8 MB scratch for hidden spikes
__device__ float g_s1[4096UL * 6272UL];

__global__ __launch_bounds__(256, 2)
void sgemm_nt_thresh(const float* __restrict__ A,   // [M, K] row-major
                     const float* __restrict__ B,   // [N, K] row-major
                     float* __restrict__ C,         // [M, N] row-major
                     int M, int N, int K) {
    __shared__ float As[BK][BM];
    __shared__ float Bs[BK][BN];

    const int tid = threadIdx.x;
    const int bm  = blockIdx.y * BM;
    const int bn  = blockIdx.x * BN;

    // Tile-load indexing: BM*BK = 2048 floats = 512 float4; 256 threads -> 2 each
    const int lr = tid >> 2;          // 0..63  (row within tile, +64 on 2nd pass)
    const int lc = (tid & 3) << 2;    // 0,4,8,12 (k offset within BK)

    // Microtile indexing: 16x16 thread grid, 8x8 accum per thread
    const int ty = tid >> 4;          // 0..15
    const int tx = tid & 15;          // 0..15

    float acc[TM][TN];
#pragma unroll
    for (int i = 0; i < TM; i++)
#pragma unroll
        for (int j = 0; j < TN; j++) acc[i][j] = 0.0f;

    for (int k0 = 0; k0 < K; k0 += BK) {
#pragma unroll
        for (int h = 0; h < 2; h++) {
            const int row = lr + h * 64;

            // A tile (M fully covered: M % 128 == 0 for both layers)
            const float4 va = *reinterpret_cast<const float4*>(
                &A[(size_t)(bm + row) * K + k0 + lc]);
            As[lc + 0][row] = va.x;
            As[lc + 1][row] = va.y;
            As[lc + 2][row] = va.z;
            As[lc + 3][row] = va.w;

            // B tile (guard: layer-2 N=500 < grid coverage 512)
            float4 vb;
            if (bn + row < N) {
                vb = *reinterpret_cast<const float4*>(
                    &B[(size_t)(bn + row) * K + k0 + lc]);
            } else {
                vb = make_float4(0.f, 0.f, 0.f, 0.f);
            }
            Bs[lc + 0][row] = vb.x;
            Bs[lc + 1][row] = vb.y;
            Bs[lc + 2][row] = vb.z;
            Bs[lc + 3][row] = vb.w;
        }
        __syncthreads();

#pragma unroll
        for (int kk = 0; kk < BK; kk++) {
            float a[TM], b[TN];
            // float4 smem loads to avoid scalar-load bank conflicts
            *reinterpret_cast<float4*>(&a[0]) =
                *reinterpret_cast<const float4*>(&As[kk][ty * TM + 0]);
            *reinterpret_cast<float4*>(&a[4]) =
                *reinterpret_cast<const float4*>(&As[kk][ty * TM + 4]);
            *reinterpret_cast<float4*>(&b[0]) =
                *reinterpret_cast<const float4*>(&Bs[kk][tx * TN + 0]);
            *reinterpret_cast<float4*>(&b[4]) =
                *reinterpret_cast<const float4*>(&Bs[kk][tx * TN + 4]);
#pragma unroll
            for (int i = 0; i < TM; i++)
#pragma unroll
                for (int j = 0; j < TN; j++)
                    acc[i][j] += a[i] * b[j];
        }
        __syncthreads();
    }

    // Epilogue: IF-neuron threshold (v >= 1.0 -> spike 1.0, else 0.0)
#pragma unroll
    for (int i = 0; i < TM; i++) {
        const int m = bm + ty * TM + i;
#pragma unroll
        for (int j = 0; j < TN; j += 4) {
            const int n = bn + tx * TN + j;
            if (n + 3 < N) {
                float4 o;
                o.x = (acc[i][j + 0] >= 1.0f) ? 1.0f : 0.0f;
                o.y = (acc[i][j + 1] >= 1.0f) ? 1.0f : 0.0f;
                o.z = (acc[i][j + 2] >= 1.0f) ? 1.0f : 0.0f;
                o.w = (acc[i][j + 3] >= 1.0f) ? 1.0f : 0.0f;
                *reinterpret_cast<float4*>(&C[(size_t)m * N + n]) = o;
            } else {
#pragma unroll
                for (int jj = 0; jj < 4; jj++) {
                    if (n + jj < N)
                        C[(size_t)m * N + n + jj] =
                            (acc[i][j + jj] >= 1.0f) ? 1.0f : 0.0f;
                }
            }
        }
    }
}

extern "C" void kernel_launch(void* const* d_in, const int* in_sizes, int n_in,
                              void* d_out, int out_size) {
    const float* x  = (const float*)d_in[0];   // [4096, 3136]
    const float* W1 = (const float*)d_in[1];   // [6272, 3136]
    const float* W2 = (const float*)d_in[2];   // [ 500, 6272]
    float* out = (float*)d_out;                // [4096,  500]

    float* s1 = nullptr;
    cudaGetSymbolAddress((void**)&s1, g_s1);   // host-side query; capture-safe

    const dim3 block(256);

    // Layer 1: [4096, 6272] = x @ W1^T, threshold
    {
        dim3 grid(6272 / BN, 4096 / BM);   // (49, 32)
        sgemm_nt_thresh<<<grid, block>>>(x, W1, s1, 4096, 6272, 3136);
    }
    // Layer 2: [4096, 500] = s1 @ W2^T, threshold
    {
        dim3 grid((500 + BN - 1) / BN, 4096 / BM);   // (4, 32)
        sgemm_nt_thresh<<<grid, block>>>(s1, W2, out, 4096, 500, 6272);
    }
}

// round 3
// speedup vs baseline: 3.6913x; 3.6913x over previous
#include <cuda_runtime.h>
#include <cuda_bf16.h>
#include <cstdint>

// ---------------------------------------------------------------------------
// TempoJelly via mma.sync (HMMA bf16): s2 = ((x @ W1^T >= 1) @ W2^T >= 1)
//   x  [4096, 3136] binary fp32  -> bf16 (exact)
//   W1 [6272, 3136] fp32 -> 3-way bf16 split (hi/mid/lo)
//   W2 [ 500, 6272] fp32 -> 3-way bf16 split, padded to 512 rows (zeros)
//   s1 [4096, 6272] binary bf16 (exact)
//   out[4096,  500] fp32 in {0,1}
//
// tcgen05 is unavailable (harness PTX stage targets compute_103, not 103a),
// so use the baseline-PTX tensor-core path: cp.async double-buffered smem,
// ldmatrix.x4 operands, mma.sync.m16n8k16.row.col.f32.bf16.bf16.f32.
// CTA tile 128x128, BK=64, 512 threads = 4x4 warps of 32x32.
// ---------------------------------------------------------------------------

#define B_ROWS 4096
#define IN_K   3136
#define FEAT   6272
#define OUT_N  500
#define OUT_PAD 512

// ---------------- static scratch (no allocations allowed) ------------------
__device__ __align__(16) __nv_bfloat16 g_xb [(size_t)B_ROWS * IN_K];
__device__ __align__(16) __nv_bfloat16 g_w1h[(size_t)FEAT * IN_K];
__device__ __align__(16) __nv_bfloat16 g_w1m[(size_t)FEAT * IN_K];
__device__ __align__(16) __nv_bfloat16 g_w1l[(size_t)FEAT * IN_K];
__device__ __align__(16) __nv_bfloat16 g_w2h[(size_t)OUT_PAD * FEAT];
__device__ __align__(16) __nv_bfloat16 g_w2m[(size_t)OUT_PAD * FEAT];
__device__ __align__(16) __nv_bfloat16 g_w2l[(size_t)OUT_PAD * FEAT];
__device__ __align__(16) __nv_bfloat16 g_s1b[(size_t)B_ROWS * FEAT];

// ---------------- PTX helpers -----------------------------------------------
__device__ __forceinline__ uint32_t smem_u32(const void* p) {
    return (uint32_t)__cvta_generic_to_shared(p);
}
__device__ __forceinline__ uint32_t sw128(uint32_t off) {
    return off ^ ((off >> 3) & 0x70);
}

#define CP_ASYNC16(smaddr, gptr)                                               \
    asm volatile("cp.async.cg.shared.global [%0], [%1], 16;"                   \
                 :: "r"(smaddr), "l"(gptr))
#define CP_COMMIT() asm volatile("cp.async.commit_group;" ::: "memory")
#define CP_WAIT(n)  asm volatile("cp.async.wait_group %0;" :: "n"(n) : "memory")

#define LDSM_X4(r, addr)                                                       \
    asm volatile("ldmatrix.sync.aligned.m8n8.x4.shared.b16 {%0,%1,%2,%3}, [%4];" \
                 : "=r"((r)[0]), "=r"((r)[1]), "=r"((r)[2]), "=r"((r)[3])      \
                 : "r"(addr))

#define MMA16816(cc, aa, b0, b1)                                               \
    asm volatile("mma.sync.aligned.m16n8k16.row.col.f32.bf16.bf16.f32 "        \
                 "{%0,%1,%2,%3},{%4,%5,%6,%7},{%8,%9},{%0,%1,%2,%3};"          \
                 : "+f"((cc)[0]), "+f"((cc)[1]), "+f"((cc)[2]), "+f"((cc)[3])  \
                 : "r"((aa)[0]), "r"((aa)[1]), "r"((aa)[2]), "r"((aa)[3]),     \
                   "r"(b0), "r"(b1))

// ---------------- conversion / split kernels --------------------------------
__global__ void cvt_x_kernel(const float* __restrict__ src,
                             __nv_bfloat16* __restrict__ dst, size_t n4) {
    size_t i = (size_t)blockIdx.x * blockDim.x + threadIdx.x;
    size_t stride = (size_t)gridDim.x * blockDim.x;
    for (; i < n4; i += stride) {
        float4 v = reinterpret_cast<const float4*>(src)[i];
        uint32_t lo = ((uint32_t)__bfloat16_as_ushort(__float2bfloat16_rn(v.x)))
                    | ((uint32_t)__bfloat16_as_ushort(__float2bfloat16_rn(v.y)) << 16);
        uint32_t hi = ((uint32_t)__bfloat16_as_ushort(__float2bfloat16_rn(v.z)))
                    | ((uint32_t)__bfloat16_as_ushort(__float2bfloat16_rn(v.w)) << 16);
        reinterpret_cast<uint2*>(dst)[i] = make_uint2(lo, hi);
    }
}

__global__ void split_w_kernel(const float* __restrict__ src,
                               __nv_bfloat16* __restrict__ dh,
                               __nv_bfloat16* __restrict__ dm,
                               __nv_bfloat16* __restrict__ dl,
                               size_t n_src4, size_t n_pad4) {
    size_t i = (size_t)blockIdx.x * blockDim.x + threadIdx.x;
    size_t stride = (size_t)gridDim.x * blockDim.x;
    for (; i < n_pad4; i += stride) {
        float w[4];
        if (i < n_src4) {
            float4 v = reinterpret_cast<const float4*>(src)[i];
            w[0] = v.x; w[1] = v.y; w[2] = v.z; w[3] = v.w;
        } else {
            w[0] = w[1] = w[2] = w[3] = 0.0f;
        }
        ushort sh[4], sm_[4], sl[4];
#pragma unroll
        for (int j = 0; j < 4; j++) {
            __nv_bfloat16 h = __float2bfloat16_rn(w[j]);
            float r = w[j] - __bfloat162float(h);
            __nv_bfloat16 m = __float2bfloat16_rn(r);
            float r2 = r - __bfloat162float(m);
            __nv_bfloat16 l = __float2bfloat16_rn(r2);
            sh[j] = __bfloat16_as_ushort(h);
            sm_[j] = __bfloat16_as_ushort(m);
            sl[j] = __bfloat16_as_ushort(l);
        }
        reinterpret_cast<uint2*>(dh)[i] = make_uint2(
            (uint32_t)sh[0] | ((uint32_t)sh[1] << 16),
            (uint32_t)sh[2] | ((uint32_t)sh[3] << 16));
        reinterpret_cast<uint2*>(dm)[i] = make_uint2(
            (uint32_t)sm_[0] | ((uint32_t)sm_[1] << 16),
            (uint32_t)sm_[2] | ((uint32_t)sm_[3] << 16));
        reinterpret_cast<uint2*>(dl)[i] = make_uint2(
            (uint32_t)sl[0] | ((uint32_t)sl[1] << 16),
            (uint32_t)sl[2] | ((uint32_t)sl[3] << 16));
    }
}

// ---------------- HMMA GEMM + threshold --------------------------------------
// Per stage: A 128x64 bf16 (16KB, SW128 rows of 128B) + 3x B 128x64 (48KB).
// Double buffered: 2 * 64KB. Dynamic smem = 1024 align slack + 131072.
#define GEMM_SMEM_BYTES (1024 + 2 * 65536)

__global__ __launch_bounds__(512, 1)
void spike_gemm(const __nv_bfloat16* __restrict__ A,
                const __nv_bfloat16* __restrict__ Bh,
                const __nv_bfloat16* __restrict__ Bm,
                const __nv_bfloat16* __restrict__ Bl,
                void* __restrict__ Cout,
                int K, int Nstride, int Nstore, int out_bf16) {
    extern __shared__ char smem[];
    const uint32_t sbase = smem_u32(smem);
    const uint32_t data0 = (sbase + 1023u) & ~1023u;

    const int tid = threadIdx.x;
    const int lane = tid & 31;
    const int wid = tid >> 5;
    const int wm = wid & 3;            // warp row (M)
    const int wn = wid >> 2;           // warp col (N)
    const int bm = blockIdx.y * 128;
    const int bn = blockIdx.x * 128;
    const int K8 = K >> 3;             // uint4 units per row
    const int nchunks = K >> 6;        // BK = 64

    // ldmatrix per-lane addressing components
    const int rA = lane & 15;                       // A row within m16 tile
    const int kA = (lane >> 4) * 16;                // A k-byte offset (0/16)
    const int rB = ((lane >> 4) << 3) | (lane & 7); // B row within n16 tile
    const int kB = ((lane >> 3) & 1) * 16;          // B k-byte offset (0/16)

    float acc[2][4][4];
#pragma unroll
    for (int mt = 0; mt < 2; mt++)
#pragma unroll
        for (int nt = 0; nt < 4; nt++)
#pragma unroll
            for (int r = 0; r < 4; r++) acc[mt][nt][r] = 0.0f;

    const __nv_bfloat16* const Bsplit[3] = {Bh, Bm, Bl};

    // ---- async load of one BK=64 chunk into buffer (chunk&1) ----
    auto load_chunk = [&](int ch) {
        const uint32_t buf = data0 + (uint32_t)(ch & 1) * 65536u;
        const int k0u = ch << 3;   // uint4 col offset = ch*64/8
#pragma unroll
        for (int t = 0; t < 2; t++) {
            const int u = tid + t * 512;
            const int row = u >> 3, ku = u & 7;
            const uint4* src = reinterpret_cast<const uint4*>(A)
                             + (size_t)(bm + row) * K8 + k0u + ku;
            CP_ASYNC16(buf + sw128(row * 128 + ku * 16), src);
        }
#pragma unroll
        for (int s = 0; s < 3; s++) {
            const uint32_t rbase = buf + 16384u * (s + 1);
#pragma unroll
            for (int t = 0; t < 2; t++) {
                const int u = tid + t * 512;
                const int row = u >> 3, ku = u & 7;
                const uint4* src = reinterpret_cast<const uint4*>(Bsplit[s])
                                 + (size_t)(bn + row) * K8 + k0u + ku;
                CP_ASYNC16(rbase + sw128(row * 128 + ku * 16), src);
            }
        }
        CP_COMMIT();
    };

    load_chunk(0);

    for (int ch = 0; ch < nchunks; ++ch) {
        if (ch + 1 < nchunks) {
            load_chunk(ch + 1);
            CP_WAIT(1);
        } else {
            CP_WAIT(0);
        }
        __syncthreads();

        const uint32_t buf = data0 + (uint32_t)(ch & 1) * 65536u;
#pragma unroll
        for (int ks = 0; ks < 4; ++ks) {
            uint32_t a[2][4];
#pragma unroll
            for (int mt = 0; mt < 2; mt++) {
                const uint32_t addr = buf
                    + sw128((wm * 32 + mt * 16 + rA) * 128 + ks * 32 + kA);
                LDSM_X4(a[mt], addr);
            }
#pragma unroll
            for (int s = 0; s < 3; s++) {
                uint32_t b[2][4];
#pragma unroll
                for (int nt2 = 0; nt2 < 2; nt2++) {
                    const uint32_t addr = buf + 16384u * (s + 1)
                        + sw128((wn * 32 + nt2 * 16 + rB) * 128 + ks * 32 + kB);
                    LDSM_X4(b[nt2], addr);
                }
#pragma unroll
                for (int mt = 0; mt < 2; mt++)
#pragma unroll
                    for (int nt = 0; nt < 4; nt++) {
                        const uint32_t b0 = b[nt >> 1][(nt & 1) * 2];
                        const uint32_t b1 = b[nt >> 1][(nt & 1) * 2 + 1];
                        MMA16816(acc[mt][nt], a[mt], b0, b1);
                    }
            }
        }
        __syncthreads();
    }

    // ---- epilogue: IF threshold ----
    if (out_bf16) {
        __nv_bfloat16* C = reinterpret_cast<__nv_bfloat16*>(Cout);
#pragma unroll
        for (int mt = 0; mt < 2; mt++) {
            const int row0 = bm + wm * 32 + mt * 16 + (lane >> 2);
#pragma unroll
            for (int nt = 0; nt < 4; nt++) {
                const int col = bn + wn * 32 + nt * 8 + (lane & 3) * 2;
                const uint32_t v0 =
                    ((acc[mt][nt][0] >= 1.0f) ? 0x3F80u : 0u)
                  | (((acc[mt][nt][1] >= 1.0f) ? 0x3F80u : 0u) << 16);
                const uint32_t v1 =
                    ((acc[mt][nt][2] >= 1.0f) ? 0x3F80u : 0u)
                  | (((acc[mt][nt][3] >= 1.0f) ? 0x3F80u : 0u) << 16);
                *reinterpret_cast<uint32_t*>(
                    C + (size_t)row0 * Nstride + col) = v0;
                *reinterpret_cast<uint32_t*>(
                    C + (size_t)(row0 + 8) * Nstride + col) = v1;
            }
        }
    } else {
        float* C = reinterpret_cast<float*>(Cout);
#pragma unroll
        for (int mt = 0; mt < 2; mt++) {
            const int row0 = bm + wm * 32 + mt * 16 + (lane >> 2);
#pragma unroll
            for (int nt = 0; nt < 4; nt++) {
                const int col = bn + wn * 32 + nt * 8 + (lane & 3) * 2;
                if (col < Nstore) {   // Nstore=500 is even; pairs all-in/out
                    float2 v0, v1;
                    v0.x = (acc[mt][nt][0] >= 1.0f) ? 1.0f : 0.0f;
                    v0.y = (acc[mt][nt][1] >= 1.0f) ? 1.0f : 0.0f;
                    v1.x = (acc[mt][nt][2] >= 1.0f) ? 1.0f : 0.0f;
                    v1.y = (acc[mt][nt][3] >= 1.0f) ? 1.0f : 0.0f;
                    *reinterpret_cast<float2*>(
                        C + (size_t)row0 * Nstore + col) = v0;
                    *reinterpret_cast<float2*>(
                        C + (size_t)(row0 + 8) * Nstore + col) = v1;
                }
            }
        }
    }
}

// ---------------- host launch -----------------------------------------------
extern "C" void kernel_launch(void* const* d_in, const int* in_sizes, int n_in,
                              void* d_out, int out_size) {
    const float* x  = (const float*)d_in[0];   // [4096, 3136]
    const float* W1 = (const float*)d_in[1];   // [6272, 3136]
    const float* W2 = (const float*)d_in[2];   // [ 500, 6272]
    float* out = (float*)d_out;                // [4096,  500]

    __nv_bfloat16 *xb, *w1h, *w1m, *w1l, *w2h, *w2m, *w2l, *s1b;
    cudaGetSymbolAddress((void**)&xb,  g_xb);
    cudaGetSymbolAddress((void**)&w1h, g_w1h);
    cudaGetSymbolAddress((void**)&w1m, g_w1m);
    cudaGetSymbolAddress((void**)&w1l, g_w1l);
    cudaGetSymbolAddress((void**)&w2h, g_w2h);
    cudaGetSymbolAddress((void**)&w2m, g_w2m);
    cudaGetSymbolAddress((void**)&w2l, g_w2l);
    cudaGetSymbolAddress((void**)&s1b, g_s1b);

    cudaFuncSetAttribute(spike_gemm,
                         cudaFuncAttributeMaxDynamicSharedMemorySize,
                         GEMM_SMEM_BYTES);

    // 1) x -> bf16 (exact: binary values)
    cvt_x_kernel<<<1024, 256>>>(x, xb, (size_t)B_ROWS * IN_K / 4);
    // 2) 3-way bf16 weight splits (W2 padded to 512 rows with zeros)
    split_w_kernel<<<2048, 256>>>(W1, w1h, w1m, w1l,
                                  (size_t)FEAT * IN_K / 4,
                                  (size_t)FEAT * IN_K / 4);
    split_w_kernel<<<1024, 256>>>(W2, w2h, w2m, w2l,
                                  (size_t)OUT_N * FEAT / 4,
                                  (size_t)OUT_PAD * FEAT / 4);

    // 3) Layer 1: s1 = (x @ W1^T >= 1), bf16 out
    {
        dim3 grid(FEAT / 128, B_ROWS / 128);     // (49, 32)
        spike_gemm<<<grid, 512, GEMM_SMEM_BYTES>>>(
            xb, w1h, w1m, w1l, s1b, IN_K, FEAT, FEAT, 1);
    }
    // 4) Layer 2: out = (s1 @ W2^T >= 1), fp32 out
    {
        dim3 grid(OUT_PAD / 128, B_ROWS / 128);  // (4, 32)
        spike_gemm<<<grid, 512, GEMM_SMEM_BYTES>>>(
            s1b, w2h, w2m, w2l, out, FEAT, OUT_N, OUT_N, 0);
    }
}

// round 4
// speedup vs baseline: 4.9295x; 1.3354x over previous
#include <cuda_runtime.h>
#include <cuda_bf16.h>
#include <cstdint>

// ---------------------------------------------------------------------------
// TempoJelly: s2 = ((x @ W1^T >= 1) @ W2^T >= 1)   (IF neuron, V_TH = 1)
//
// Strategy (R4):
//  - activations binary -> exact in bf16
//  - weights: 2-way bf16 split (hi, mid). The dropped residual per output is
//    bounded by eps_col = sum_k |w - hi - mid| (binary activations!), so any
//    element with |acc - 1| > eps is provably on the correct threshold side.
//  - near-threshold elements (|acc-1| <= eps, ~1e-4 of all) are pushed to a
//    candidate list and recomputed exactly in fp32 by a fixup kernel.
//  - GEMM: mma.sync m16n8k16 bf16, 256 thr (8 warps, 64x32 warp tiles),
//    CTA 128x128, BK=64, 4-stage cp.async pipeline (192KB smem).
// ---------------------------------------------------------------------------

#define B_ROWS 4096
#define IN_K   3136
#define FEAT   6272
#define OUT_N  500
#define OUT_PAD 512
#define MAXC   (4 << 20)
#define EPS_MARGIN 5e-5f

// ---------------- static scratch --------------------------------------------
__device__ __align__(16) __nv_bfloat16 g_xb [(size_t)B_ROWS * IN_K];
__device__ __align__(16) __nv_bfloat16 g_w1h[(size_t)FEAT * IN_K];
__device__ __align__(16) __nv_bfloat16 g_w1m[(size_t)FEAT * IN_K];
__device__ __align__(16) __nv_bfloat16 g_w2h[(size_t)OUT_PAD * FEAT];
__device__ __align__(16) __nv_bfloat16 g_w2m[(size_t)OUT_PAD * FEAT];
__device__ __align__(16) __nv_bfloat16 g_s1b[(size_t)B_ROWS * FEAT];
__device__ float    g_eps1[FEAT];
__device__ float    g_eps2[OUT_PAD];
__device__ uint32_t g_cand1[MAXC];
__device__ uint32_t g_cand2[MAXC];
__device__ uint32_t g_cnt1;
__device__ uint32_t g_cnt2;

// ---------------- PTX helpers ------------------------------------------------
__device__ __forceinline__ uint32_t smem_u32(const void* p) {
    return (uint32_t)__cvta_generic_to_shared(p);
}
__device__ __forceinline__ uint32_t sw128(uint32_t off) {
    return off ^ ((off >> 3) & 0x70);
}

#define CP_ASYNC16(smaddr, gptr)                                               \
    asm volatile("cp.async.cg.shared.global [%0], [%1], 16;"                   \
                 :: "r"(smaddr), "l"(gptr))
#define CP_COMMIT() asm volatile("cp.async.commit_group;" ::: "memory")
#define CP_WAIT(n)  asm volatile("cp.async.wait_group %0;" :: "n"(n) : "memory")

#define LDSM_X4(r, addr)                                                       \
    asm volatile("ldmatrix.sync.aligned.m8n8.x4.shared.b16 {%0,%1,%2,%3}, [%4];" \
                 : "=r"((r)[0]), "=r"((r)[1]), "=r"((r)[2]), "=r"((r)[3])      \
                 : "r"(addr))

#define MMA16816(cc, aa, b0, b1)                                               \
    asm volatile("mma.sync.aligned.m16n8k16.row.col.f32.bf16.bf16.f32 "        \
                 "{%0,%1,%2,%3},{%4,%5,%6,%7},{%8,%9},{%0,%1,%2,%3};"          \
                 : "+f"((cc)[0]), "+f"((cc)[1]), "+f"((cc)[2]), "+f"((cc)[3])  \
                 : "r"((aa)[0]), "r"((aa)[1]), "r"((aa)[2]), "r"((aa)[3]),     \
                   "r"(b0), "r"(b1))

// ---------------- prep kernels -----------------------------------------------
__global__ void reset_kernel() {
    if (threadIdx.x == 0) { g_cnt1 = 0; g_cnt2 = 0; }
}

__global__ void cvt_x_kernel(const float* __restrict__ src,
                             __nv_bfloat16* __restrict__ dst, size_t n4) {
    size_t i = (size_t)blockIdx.x * blockDim.x + threadIdx.x;
    size_t stride = (size_t)gridDim.x * blockDim.x;
    for (; i < n4; i += stride) {
        float4 v = reinterpret_cast<const float4*>(src)[i];
        uint32_t lo = ((uint32_t)__bfloat16_as_ushort(__float2bfloat16_rn(v.x)))
                    | ((uint32_t)__bfloat16_as_ushort(__float2bfloat16_rn(v.y)) << 16);
        uint32_t hi = ((uint32_t)__bfloat16_as_ushort(__float2bfloat16_rn(v.z)))
                    | ((uint32_t)__bfloat16_as_ushort(__float2bfloat16_rn(v.w)) << 16);
        reinterpret_cast<uint2*>(dst)[i] = make_uint2(lo, hi);
    }
}

// One warp per weight row: 2-way bf16 split + per-row residual-abs-sum bound.
// Pad rows (>= n_rows) get zero splits and eps = 0.
__global__ void split2_w_kernel(const float* __restrict__ src,
                                __nv_bfloat16* __restrict__ dh,
                                __nv_bfloat16* __restrict__ dm,
                                float* __restrict__ eps,
                                int n_rows, int K) {
    const int warp = threadIdx.x >> 5;
    const int lane = threadIdx.x & 31;
    const int row  = blockIdx.x * 8 + warp;
    const int K4   = K >> 2;
    float rsum = 0.0f;
    for (int i = lane; i < K4; i += 32) {
        float w[4] = {0.f, 0.f, 0.f, 0.f};
        if (row < n_rows) {
            float4 v = reinterpret_cast<const float4*>(src)[(size_t)row * K4 + i];
            w[0] = v.x; w[1] = v.y; w[2] = v.z; w[3] = v.w;
        }
        ushort sh[4], sm_[4];
#pragma unroll
        for (int j = 0; j < 4; j++) {
            __nv_bfloat16 h = __float2bfloat16_rn(w[j]);
            float r = w[j] - __bfloat162float(h);
            __nv_bfloat16 m = __float2bfloat16_rn(r);
            rsum += fabsf(r - __bfloat162float(m));
            sh[j] = __bfloat16_as_ushort(h);
            sm_[j] = __bfloat16_as_ushort(m);
        }
        reinterpret_cast<uint2*>(dh)[(size_t)row * K4 + i] = make_uint2(
            (uint32_t)sh[0] | ((uint32_t)sh[1] << 16),
            (uint32_t)sh[2] | ((uint32_t)sh[3] << 16));
        reinterpret_cast<uint2*>(dm)[(size_t)row * K4 + i] = make_uint2(
            (uint32_t)sm_[0] | ((uint32_t)sm_[1] << 16),
            (uint32_t)sm_[2] | ((uint32_t)sm_[3] << 16));
    }
#pragma unroll
    for (int o = 16; o; o >>= 1) rsum += __shfl_xor_sync(~0u, rsum, o);
    if (lane == 0)
        eps[row] = (row < n_rows) ? (rsum + EPS_MARGIN) : 0.0f;
}

// ---------------- HMMA GEMM + threshold + candidate detection -----------------
// Stage: A 128x64 (16KB) + Bh 128x64 (16KB) + Bm (16KB) = 48KB; 4 stages.
#define STAGE_BYTES 49152
#define NSTAGES 4
#define GEMM_SMEM_BYTES (1024 + NSTAGES * STAGE_BYTES)

__global__ __launch_bounds__(256, 1)
void spike_gemm(const __nv_bfloat16* __restrict__ A,
                const __nv_bfloat16* __restrict__ Bh,
                const __nv_bfloat16* __restrict__ Bm,
                const float* __restrict__ eps,
                void* __restrict__ Cout,
                uint32_t* __restrict__ cand,
                uint32_t* __restrict__ cnt,
                int K, int Nstride, int Nstore, int out_bf16) {
    extern __shared__ char smem[];
    const uint32_t sbase = smem_u32(smem);
    const uint32_t data0 = (sbase + 1023u) & ~1023u;

    const int tid  = threadIdx.x;
    const int lane = tid & 31;
    const int wid  = tid >> 5;
    const int wm   = wid & 1;          // warp row (2 x 64)
    const int wn   = wid >> 1;         // warp col (4 x 32)
    const int bm   = blockIdx.y * 128;
    const int bn   = blockIdx.x * 128;
    const int K8   = K >> 3;
    const int nchunks = K >> 6;

    // ldmatrix lane addressing
    const int rA = lane & 15;
    const int kA = (lane >> 4) * 16;
    const int rB = ((lane >> 4) << 3) | (lane & 7);
    const int kB = ((lane >> 3) & 1) * 16;

    float acc[4][4][4];
#pragma unroll
    for (int mt = 0; mt < 4; mt++)
#pragma unroll
        for (int nt = 0; nt < 4; nt++)
#pragma unroll
            for (int r = 0; r < 4; r++) acc[mt][nt][r] = 0.0f;

    auto load_chunk = [&](int ch) {
        const uint32_t buf = data0 + (uint32_t)(ch & (NSTAGES - 1)) * STAGE_BYTES;
        const int k0u = ch << 3;
#pragma unroll
        for (int t = 0; t < 4; ++t) {
            const int u = tid + t * 256;
            const int row = u >> 3, ku = u & 7;
            const uint4* src = reinterpret_cast<const uint4*>(A)
                             + (size_t)(bm + row) * K8 + k0u + ku;
            CP_ASYNC16(buf + sw128(row * 128 + ku * 16), src);
        }
#pragma unroll
        for (int t = 0; t < 4; ++t) {
            const int u = tid + t * 256;
            const int row = u >> 3, ku = u & 7;
            const uint4* src = reinterpret_cast<const uint4*>(Bh)
                             + (size_t)(bn + row) * K8 + k0u + ku;
            CP_ASYNC16(buf + 16384u + sw128(row * 128 + ku * 16), src);
        }
#pragma unroll
        for (int t = 0; t < 4; ++t) {
            const int u = tid + t * 256;
            const int row = u >> 3, ku = u & 7;
            const uint4* src = reinterpret_cast<const uint4*>(Bm)
                             + (size_t)(bn + row) * K8 + k0u + ku;
            CP_ASYNC16(buf + 32768u + sw128(row * 128 + ku * 16), src);
        }
    };

    // prologue: 3 stages in flight
    load_chunk(0); CP_COMMIT();
    load_chunk(1); CP_COMMIT();
    load_chunk(2); CP_COMMIT();

    for (int ch = 0; ch < nchunks; ++ch) {
        CP_WAIT(2);           // group ch complete (one commit per iter below)
        __syncthreads();

        if (ch + 3 < nchunks) load_chunk(ch + 3);
        CP_COMMIT();          // empty group in tail keeps wait count exact

        const uint32_t buf = data0 + (uint32_t)(ch & (NSTAGES - 1)) * STAGE_BYTES;
#pragma unroll
        for (int ks = 0; ks < 4; ++ks) {
            uint32_t a[4][4];
#pragma unroll
            for (int mt = 0; mt < 4; mt++) {
                const uint32_t addr = buf
                    + sw128((wm * 64 + mt * 16 + rA) * 128 + ks * 32 + kA);
                LDSM_X4(a[mt], addr);
            }
#pragma unroll
            for (int s = 0; s < 2; s++) {
                uint32_t b[2][4];
#pragma unroll
                for (int nt2 = 0; nt2 < 2; nt2++) {
                    const uint32_t addr = buf + 16384u * (s + 1)
                        + sw128((wn * 32 + nt2 * 16 + rB) * 128 + ks * 32 + kB);
                    LDSM_X4(b[nt2], addr);
                }
#pragma unroll
                for (int mt = 0; mt < 4; mt++)
#pragma unroll
                    for (int nt = 0; nt < 4; nt++) {
                        const uint32_t b0 = b[nt >> 1][(nt & 1) * 2];
                        const uint32_t b1 = b[nt >> 1][(nt & 1) * 2 + 1];
                        MMA16816(acc[mt][nt], a[mt], b0, b1);
                    }
            }
        }
    }

    // ---- epilogue: threshold + near-threshold candidate capture ----
    float ev[4][2];
#pragma unroll
    for (int nt = 0; nt < 4; nt++) {
        const int col = bn + wn * 32 + nt * 8 + (lane & 3) * 2;
        ev[nt][0] = eps[col];
        ev[nt][1] = eps[col + 1];
    }

#pragma unroll
    for (int mt = 0; mt < 4; mt++) {
        const int row0 = bm + wm * 64 + mt * 16 + (lane >> 2);
#pragma unroll
        for (int nt = 0; nt < 4; nt++) {
            const int col = bn + wn * 32 + nt * 8 + (lane & 3) * 2;
            // candidate pushes (rare)
#pragma unroll
            for (int r = 0; r < 4; r++) {
                const float v = acc[mt][nt][r];
                const float e = ev[nt][r & 1];
                if (fabsf(v - 1.0f) <= e) {
                    const int rr = row0 + (r >> 1) * 8;
                    const int cc = col + (r & 1);
                    const uint32_t idx = atomicAdd(cnt, 1u);
                    if (idx < MAXC)
                        cand[idx] = ((uint32_t)rr << 16) | (uint32_t)cc;
                }
            }
            if (out_bf16) {
                __nv_bfloat16* C = reinterpret_cast<__nv_bfloat16*>(Cout);
                const uint32_t v0 =
                    ((acc[mt][nt][0] >= 1.0f) ? 0x3F80u : 0u)
                  | (((acc[mt][nt][1] >= 1.0f) ? 0x3F80u : 0u) << 16);
                const uint32_t v1 =
                    ((acc[mt][nt][2] >= 1.0f) ? 0x3F80u : 0u)
                  | (((acc[mt][nt][3] >= 1.0f) ? 0x3F80u : 0u) << 16);
                *reinterpret_cast<uint32_t*>(
                    C + (size_t)row0 * Nstride + col) = v0;
                *reinterpret_cast<uint32_t*>(
                    C + (size_t)(row0 + 8) * Nstride + col) = v1;
            } else if (col < Nstore) {
                float* C = reinterpret_cast<float*>(Cout);
                float2 v0, v1;
                v0.x = (acc[mt][nt][0] >= 1.0f) ? 1.0f : 0.0f;
                v0.y = (acc[mt][nt][1] >= 1.0f) ? 1.0f : 0.0f;
                v1.x = (acc[mt][nt][2] >= 1.0f) ? 1.0f : 0.0f;
                v1.y = (acc[mt][nt][3] >= 1.0f) ? 1.0f : 0.0f;
                *reinterpret_cast<float2*>(C + (size_t)row0 * Nstore + col) = v0;
                *reinterpret_cast<float2*>(C + (size_t)(row0 + 8) * Nstore + col) = v1;
            }
        }
    }
}

// ---------------- exact fp32 fixup of near-threshold elements ------------------
__global__ void fixup_kernel(const uint32_t* __restrict__ cand,
                             const uint32_t* __restrict__ cnt,
                             const __nv_bfloat16* __restrict__ A,
                             const float* __restrict__ W,
                             int K, void* __restrict__ Cout,
                             int Nstride, int out_bf16) {
    const int gw   = (blockIdx.x * blockDim.x + threadIdx.x) >> 5;
    const int lane = threadIdx.x & 31;
    const int nw   = (gridDim.x * blockDim.x) >> 5;
    uint32_t n = *cnt;
    if (n > MAXC) n = MAXC;
    for (uint32_t i = gw; i < n; i += nw) {
        const uint32_t e = cand[i];
        const int row = (int)(e >> 16);
        const int col = (int)(e & 0xFFFFu);
        float s = 0.0f;
        for (int k = lane; k < K; k += 32)
            s += __bfloat162float(A[(size_t)row * K + k]) * W[(size_t)col * K + k];
#pragma unroll
        for (int o = 16; o; o >>= 1) s += __shfl_xor_sync(~0u, s, o);
        if (lane == 0) {
            const float spike = (s >= 1.0f) ? 1.0f : 0.0f;
            if (out_bf16)
                reinterpret_cast<__nv_bfloat16*>(Cout)[(size_t)row * Nstride + col] =
                    __float2bfloat16(spike);
            else
                reinterpret_cast<float*>(Cout)[(size_t)row * Nstride + col] = spike;
        }
    }
}

// ---------------- host launch --------------------------------------------------
extern "C" void kernel_launch(void* const* d_in, const int* in_sizes, int n_in,
                              void* d_out, int out_size) {
    const float* x  = (const float*)d_in[0];   // [4096, 3136]
    const float* W1 = (const float*)d_in[1];   // [6272, 3136]
    const float* W2 = (const float*)d_in[2];   // [ 500, 6272]
    float* out = (float*)d_out;                // [4096,  500]

    __nv_bfloat16 *xb, *w1h, *w1m, *w2h, *w2m, *s1b;
    float *eps1, *eps2;
    uint32_t *cand1, *cand2, *cnt1, *cnt2;
    cudaGetSymbolAddress((void**)&xb,  g_xb);
    cudaGetSymbolAddress((void**)&w1h, g_w1h);
    cudaGetSymbolAddress((void**)&w1m, g_w1m);
    cudaGetSymbolAddress((void**)&w2h, g_w2h);
    cudaGetSymbolAddress((void**)&w2m, g_w2m);
    cudaGetSymbolAddress((void**)&s1b, g_s1b);
    cudaGetSymbolAddress((void**)&eps1, g_eps1);
    cudaGetSymbolAddress((void**)&eps2, g_eps2);
    cudaGetSymbolAddress((void**)&cand1, g_cand1);
    cudaGetSymbolAddress((void**)&cand2, g_cand2);
    cudaGetSymbolAddress((void**)&cnt1, g_cnt1);
    cudaGetSymbolAddress((void**)&cnt2, g_cnt2);

    cudaFuncSetAttribute(spike_gemm,
                         cudaFuncAttributeMaxDynamicSharedMemorySize,
                         GEMM_SMEM_BYTES);

    reset_kernel<<<1, 32>>>();
    cvt_x_kernel<<<1024, 256>>>(x, xb, (size_t)B_ROWS * IN_K / 4);
    split2_w_kernel<<<FEAT / 8, 256>>>(W1, w1h, w1m, eps1, FEAT, IN_K);
    split2_w_kernel<<<OUT_PAD / 8, 256>>>(W2, w2h, w2m, eps2, OUT_N, FEAT);

    // Layer 1: s1 = (x @ W1^T >= 1)  [bf16 out] + candidates
    {
        dim3 grid(FEAT / 128, B_ROWS / 128);     // (49, 32)
        spike_gemm<<<grid, 256, GEMM_SMEM_BYTES>>>(
            xb, w1h, w1m, eps1, s1b, cand1, cnt1, IN_K, FEAT, FEAT, 1);
    }
    fixup_kernel<<<256, 256>>>(cand1, cnt1, xb, W1, IN_K, s1b, FEAT, 1);

    // Layer 2: out = (s1 @ W2^T >= 1)  [fp32 out] + candidates
    {
        dim3 grid(OUT_PAD / 128, B_ROWS / 128);  // (4, 32)
        spike_gemm<<<grid, 256, GEMM_SMEM_BYTES>>>(
            s1b, w2h, w2m, eps2, out, cand2, cnt2, FEAT, OUT_N, OUT_N, 0);
    }
    fixup_kernel<<<256, 256>>>(cand2, cnt2, s1b, W2, FEAT, out, OUT_N, 0);
}